// round 1
// baseline (speedup 1.0000x reference)
#include <cuda_runtime.h>

// Problem constants (MultiHeadAttention: B=2,S=2048,E=1024,H=16,D=64)
constexpr int Bb = 2;
constexpr int Ss = 2048;
constexpr int Ee = 1024;
constexpr int Hh = 16;
constexpr int Dd = 64;

// Scratch (device globals; no allocation allowed)
__device__ float g_qh[Bb * Hh * Ss * Dd];   // [B,H,S,D]
__device__ float g_kh[Bb * Hh * Ss * Dd];
__device__ float g_vh[Bb * Hh * Ss * Dd];
__device__ float g_ctx[Bb * Ss * Ee];       // [B,S,E]

// ---------------------------------------------------------------------------
// SGEMM: C[m,n] = sum_k A[m,k] * W[n,k] + bias[n]
// A: [M,K] row-major, W: [N,K] row-major (torch Linear weight), M=4096, N=K=1024
// Tile 64x64, BK=16, 256 threads, 4x4 per-thread register tile.
// HEAD_STORE: store into [B,H,S,D] layout instead of [M,N].
// ---------------------------------------------------------------------------
template <bool HEAD_STORE>
__global__ __launch_bounds__(256) void sgemm_nt(const float* __restrict__ A,
                                                const float* __restrict__ W,
                                                const float* __restrict__ bias,
                                                float* __restrict__ C, int K) {
    __shared__ float As[16][64];  // [k][m] transposed
    __shared__ float Wsm[16][64]; // [k][n] transposed

    const int tx = threadIdx.x;   // 0..15  (n direction)
    const int ty = threadIdx.y;   // 0..15  (m direction)
    const int tid = ty * 16 + tx;
    const int m0 = blockIdx.y * 64;
    const int n0 = blockIdx.x * 64;

    const int lr = tid >> 2;         // 0..63 row within tile
    const int lk = (tid & 3) << 2;   // 0,4,8,12 k offset

    const float* Ap = A + (long)(m0 + lr) * K + lk;
    const float* Wp = W + (long)(n0 + lr) * K + lk;

    float acc[4][4];
#pragma unroll
    for (int i = 0; i < 4; ++i)
#pragma unroll
        for (int j = 0; j < 4; ++j) acc[i][j] = 0.f;

    for (int kt = 0; kt < K; kt += 16) {
        float4 av = *(const float4*)(Ap + kt);
        float4 wv = *(const float4*)(Wp + kt);
        __syncthreads();
        As[lk + 0][lr] = av.x; As[lk + 1][lr] = av.y;
        As[lk + 2][lr] = av.z; As[lk + 3][lr] = av.w;
        Wsm[lk + 0][lr] = wv.x; Wsm[lk + 1][lr] = wv.y;
        Wsm[lk + 2][lr] = wv.z; Wsm[lk + 3][lr] = wv.w;
        __syncthreads();
#pragma unroll
        for (int k = 0; k < 16; ++k) {
            float4 a = *(const float4*)&As[k][ty << 2];
            float4 w = *(const float4*)&Wsm[k][tx << 2];
            acc[0][0] += a.x * w.x; acc[0][1] += a.x * w.y;
            acc[0][2] += a.x * w.z; acc[0][3] += a.x * w.w;
            acc[1][0] += a.y * w.x; acc[1][1] += a.y * w.y;
            acc[1][2] += a.y * w.z; acc[1][3] += a.y * w.w;
            acc[2][0] += a.z * w.x; acc[2][1] += a.z * w.y;
            acc[2][2] += a.z * w.z; acc[2][3] += a.z * w.w;
            acc[3][0] += a.w * w.x; acc[3][1] += a.w * w.y;
            acc[3][2] += a.w * w.z; acc[3][3] += a.w * w.w;
        }
    }

    float4 bv = *(const float4*)&bias[n0 + (tx << 2)];
#pragma unroll
    for (int i = 0; i < 4; ++i) {
        const int m = m0 + (ty << 2) + i;
        float4 r;
        r.x = acc[i][0] + bv.x;
        r.y = acc[i][1] + bv.y;
        r.z = acc[i][2] + bv.z;
        r.w = acc[i][3] + bv.w;
        if (HEAD_STORE) {
            // C layout [B,H,S,D]; n0 is head-aligned (64 | n0)
            const int b = m / Ss, s = m % Ss;
            const int h = n0 >> 6;
            *(float4*)&C[(((long)(b * Hh + h) * Ss + s) * Dd) + (tx << 2)] = r;
        } else {
            *(float4*)&C[(long)m * Ee + n0 + (tx << 2)] = r;
        }
    }
}

// ---------------------------------------------------------------------------
// Fused attention: per (b,h), 64-query tile per CTA, stream 64-key tiles.
// Online softmax, fp32 everywhere. Mask: [B,1,S,S] int32, 0 -> -1e10.
// Dynamic smem: Qt[64][64] (d-major), Kt[64][64] (d-major), Vs[64][64] (j-major),
//               Ps[64][64] (row-major)  = 64 KB
// ---------------------------------------------------------------------------
__global__ __launch_bounds__(256) void attn_kernel(const int* __restrict__ mask,
                                                   const float* __restrict__ qh,
                                                   const float* __restrict__ kh,
                                                   const float* __restrict__ vh,
                                                   float* __restrict__ ctx) {
    extern __shared__ float sm[];
    float* Qt = sm;            // Qt[d*64 + r]
    float* Kt = sm + 4096;     // Kt[d*64 + c]
    float* Vs = sm + 8192;     // Vs[j*64 + d]
    float* Ps = sm + 12288;    // Ps[r*64 + j]

    const int tx = threadIdx.x;  // 0..15
    const int ty = threadIdx.y;  // 0..15
    const int tid = ty * 16 + tx;
    const int q0 = blockIdx.x * 64;
    const int bh = blockIdx.y;
    const int b = bh / Hh;
    const int h = bh % Hh;

    const float* Q = qh + (long)bh * Ss * Dd;
    const float* Kg = kh + (long)bh * Ss * Dd;
    const float* Vg = vh + (long)bh * Ss * Dd;
    const int* Mb = mask + (long)b * Ss * Ss;

    // Load 64x64 Q tile, transposed to d-major
    {
        const int r = tid >> 2;
        const int d0 = (tid & 3) << 4;
#pragma unroll
        for (int u = 0; u < 4; ++u) {
            float4 v = *(const float4*)&Q[(long)(q0 + r) * Dd + d0 + u * 4];
            Qt[(d0 + u * 4 + 0) * 64 + r] = v.x;
            Qt[(d0 + u * 4 + 1) * 64 + r] = v.y;
            Qt[(d0 + u * 4 + 2) * 64 + r] = v.z;
            Qt[(d0 + u * 4 + 3) * 64 + r] = v.w;
        }
    }

    float m_i[4], l_i[4], acc[4][4];
#pragma unroll
    for (int i = 0; i < 4; ++i) {
        m_i[i] = -1e30f;
        l_i[i] = 0.f;
#pragma unroll
        for (int j = 0; j < 4; ++j) acc[i][j] = 0.f;
    }

    const float scale = 0.125f;  // 1/sqrt(64)

    for (int k0 = 0; k0 < Ss; k0 += 64) {
        __syncthreads();  // previous iteration's PV reads done
        // Load K tile transposed (d-major) and V tile j-major
        {
            const int r = tid >> 2;
            const int d0 = (tid & 3) << 4;
#pragma unroll
            for (int u = 0; u < 4; ++u) {
                float4 kv = *(const float4*)&Kg[(long)(k0 + r) * Dd + d0 + u * 4];
                Kt[(d0 + u * 4 + 0) * 64 + r] = kv.x;
                Kt[(d0 + u * 4 + 1) * 64 + r] = kv.y;
                Kt[(d0 + u * 4 + 2) * 64 + r] = kv.z;
                Kt[(d0 + u * 4 + 3) * 64 + r] = kv.w;
                float4 vv = *(const float4*)&Vg[(long)(k0 + r) * Dd + d0 + u * 4];
                *(float4*)&Vs[r * 64 + d0 + u * 4] = vv;
            }
        }
        __syncthreads();

        // Scores: s[i][j] = sum_d Qt[d][ty*4+i] * Kt[d][tx*4+j]
        float s[4][4];
#pragma unroll
        for (int i = 0; i < 4; ++i)
#pragma unroll
            for (int j = 0; j < 4; ++j) s[i][j] = 0.f;

#pragma unroll 16
        for (int d = 0; d < 64; ++d) {
            float4 a = *(const float4*)&Qt[d * 64 + (ty << 2)];
            float4 kk = *(const float4*)&Kt[d * 64 + (tx << 2)];
            s[0][0] += a.x * kk.x; s[0][1] += a.x * kk.y;
            s[0][2] += a.x * kk.z; s[0][3] += a.x * kk.w;
            s[1][0] += a.y * kk.x; s[1][1] += a.y * kk.y;
            s[1][2] += a.y * kk.z; s[1][3] += a.y * kk.w;
            s[2][0] += a.z * kk.x; s[2][1] += a.z * kk.y;
            s[2][2] += a.z * kk.z; s[2][3] += a.z * kk.w;
            s[3][0] += a.w * kk.x; s[3][1] += a.w * kk.y;
            s[3][2] += a.w * kk.z; s[3][3] += a.w * kk.w;
        }

        // Mask + online softmax update (rows ty*4+i; 16 tx lanes hold one row)
#pragma unroll
        for (int i = 0; i < 4; ++i) {
            int4 mv = *(const int4*)&Mb[(long)(q0 + (ty << 2) + i) * Ss + k0 + (tx << 2)];
            s[i][0] = mv.x ? s[i][0] * scale : -1e10f;
            s[i][1] = mv.y ? s[i][1] * scale : -1e10f;
            s[i][2] = mv.z ? s[i][2] * scale : -1e10f;
            s[i][3] = mv.w ? s[i][3] * scale : -1e10f;

            float mx = fmaxf(fmaxf(s[i][0], s[i][1]), fmaxf(s[i][2], s[i][3]));
#pragma unroll
            for (int off = 8; off; off >>= 1)
                mx = fmaxf(mx, __shfl_xor_sync(0xffffffffu, mx, off));

            const float mnew = fmaxf(m_i[i], mx);
            const float alpha = __expf(m_i[i] - mnew);
            m_i[i] = mnew;

            float rs = 0.f;
#pragma unroll
            for (int j = 0; j < 4; ++j) {
                float p = __expf(s[i][j] - mnew);
                s[i][j] = p;
                rs += p;
            }
#pragma unroll
            for (int off = 8; off; off >>= 1)
                rs += __shfl_xor_sync(0xffffffffu, rs, off);

            l_i[i] = l_i[i] * alpha + rs;
#pragma unroll
            for (int j = 0; j < 4; ++j) acc[i][j] *= alpha;

            *(float4*)&Ps[((ty << 2) + i) * 64 + (tx << 2)] =
                make_float4(s[i][0], s[i][1], s[i][2], s[i][3]);
        }
        __syncthreads();

        // PV: acc[i][jj] += sum_j Ps[r][j] * Vs[j][tx*4+jj]
#pragma unroll 16
        for (int j = 0; j < 64; ++j) {
            float4 v = *(const float4*)&Vs[j * 64 + (tx << 2)];
            float p0 = Ps[((ty << 2) + 0) * 64 + j];
            float p1 = Ps[((ty << 2) + 1) * 64 + j];
            float p2 = Ps[((ty << 2) + 2) * 64 + j];
            float p3 = Ps[((ty << 2) + 3) * 64 + j];
            acc[0][0] += p0 * v.x; acc[0][1] += p0 * v.y;
            acc[0][2] += p0 * v.z; acc[0][3] += p0 * v.w;
            acc[1][0] += p1 * v.x; acc[1][1] += p1 * v.y;
            acc[1][2] += p1 * v.z; acc[1][3] += p1 * v.w;
            acc[2][0] += p2 * v.x; acc[2][1] += p2 * v.y;
            acc[2][2] += p2 * v.z; acc[2][3] += p2 * v.w;
            acc[3][0] += p3 * v.x; acc[3][1] += p3 * v.y;
            acc[3][2] += p3 * v.z; acc[3][3] += p3 * v.w;
        }
    }

    // Epilogue: normalize and store into ctx [B,S,E] with E-col = h*64 + d
#pragma unroll
    for (int i = 0; i < 4; ++i) {
        const float inv = 1.f / l_i[i];
        const int srow = q0 + (ty << 2) + i;
        float4 r = make_float4(acc[i][0] * inv, acc[i][1] * inv,
                               acc[i][2] * inv, acc[i][3] * inv);
        *(float4*)&g_ctx[((long)(b * Ss + srow)) * Ee + h * Dd + (tx << 2)] = r;
    }
    (void)ctx;
}

// ---------------------------------------------------------------------------
extern "C" void kernel_launch(void* const* d_in, const int* in_sizes, int n_in,
                              void* d_out, int out_size) {
    const float* q  = (const float*)d_in[0];
    const float* k  = (const float*)d_in[1];
    const float* v  = (const float*)d_in[2];
    const int* mask = (const int*)d_in[3];
    const float* Wq = (const float*)d_in[4];
    const float* bq = (const float*)d_in[5];
    const float* Wk = (const float*)d_in[6];
    const float* bk = (const float*)d_in[7];
    const float* Wv = (const float*)d_in[8];
    const float* bv = (const float*)d_in[9];
    const float* Wo = (const float*)d_in[10];
    const float* bo = (const float*)d_in[11];
    float* out = (float*)d_out;

    float *qh, *kh, *vh, *ctx;
    cudaGetSymbolAddress((void**)&qh, g_qh);
    cudaGetSymbolAddress((void**)&kh, g_kh);
    cudaGetSymbolAddress((void**)&vh, g_vh);
    cudaGetSymbolAddress((void**)&ctx, g_ctx);

    dim3 blk(16, 16);
    dim3 gproj(Ee / 64, (Bb * Ss) / 64);

    sgemm_nt<true><<<gproj, blk>>>(q, Wq, bq, qh, Ee);
    sgemm_nt<true><<<gproj, blk>>>(k, Wk, bk, kh, Ee);
    sgemm_nt<true><<<gproj, blk>>>(v, Wv, bv, vh, Ee);

    cudaFuncSetAttribute(attn_kernel, cudaFuncAttributeMaxDynamicSharedMemorySize,
                         64 * 1024);
    dim3 gattn(Ss / 64, Bb * Hh);
    attn_kernel<<<gattn, blk, 64 * 1024>>>(mask, qh, kh, vh, ctx);

    sgemm_nt<false><<<gproj, blk>>>(ctx, Wo, bo, out, Ee);
}

// round 3
// speedup vs baseline: 1.5257x; 1.5257x over previous
#include <cuda_runtime.h>
#include <cstdint>

// Problem constants (MultiHeadAttention: B=2,S=2048,E=1024,H=16,D=64)
constexpr int Bb = 2;
constexpr int Ss = 2048;
constexpr int Ee = 1024;
constexpr int Hh = 16;
constexpr int Dd = 64;

// Scratch (device globals; no allocation allowed)
__device__ float g_qh[Bb * Hh * Ss * Dd];   // [B,H,S,D]
__device__ float g_kh[Bb * Hh * Ss * Dd];
__device__ float g_vh[Bb * Hh * Ss * Dd];
__device__ float g_ctx[Bb * Ss * Ee];       // [B,S,E]

__device__ __forceinline__ uint32_t f2tf32(float x) {
    uint32_t r;
    asm("cvt.rna.tf32.f32 %0, %1;" : "=r"(r) : "f"(x));
    return r;
}

#define MMA_TF32(c, a, b)                                                      \
    asm volatile(                                                              \
        "mma.sync.aligned.m16n8k8.row.col.f32.tf32.tf32.f32 "                  \
        "{%0,%1,%2,%3}, {%4,%5,%6,%7}, {%8,%9}, {%0,%1,%2,%3};"                \
        : "+f"((c)[0]), "+f"((c)[1]), "+f"((c)[2]), "+f"((c)[3])               \
        : "r"((a)[0]), "r"((a)[1]), "r"((a)[2]), "r"((a)[3]),                  \
          "r"((b)[0]), "r"((b)[1]))

// ---------------------------------------------------------------------------
// tf32 mma.sync GEMM: C[m,n] = sum_k A[m,k]*W[n,k] + bias[n]
// M=4096, N=K=1024. CTA 128x128, BK=16, 8 warps (2x4), warp tile 64x32.
// Double-buffered smem, stride 20 floats (fragment loads hit 32 distinct banks).
// ---------------------------------------------------------------------------
template <bool HEAD_STORE>
__global__ __launch_bounds__(256) void gemm_mma(const float* __restrict__ A,
                                                const float* __restrict__ W,
                                                const float* __restrict__ bias,
                                                float* __restrict__ C) {
    __shared__ uint32_t sA[2][128 * 20];
    __shared__ uint32_t sB[2][128 * 20];

    const int tid = threadIdx.x;
    const int lane = tid & 31;
    const int g = lane >> 2, tg = lane & 3;
    const int w = tid >> 5;
    const int wm = (w >> 2) * 64;   // warp m origin (0 or 64)
    const int wn = (w & 3) * 32;    // warp n origin (0,32,64,96)
    const int m0 = blockIdx.y * 128, n0 = blockIdx.x * 128;

    float acc[4][4][4];
#pragma unroll
    for (int mt = 0; mt < 4; ++mt)
#pragma unroll
        for (int nt = 0; nt < 4; ++nt)
#pragma unroll
            for (int i = 0; i < 4; ++i) acc[mt][nt][i] = 0.f;

    float4 ra[2], rb[2];

    auto fetch = [&](int kt) {
        const int kb = kt * 16;
#pragma unroll
        for (int i = 0; i < 2; ++i) {
            const int v = tid + i * 256;
            const int row = v >> 2, c = (v & 3) * 4;
            ra[i] = *(const float4*)&A[(long)(m0 + row) * Ee + kb + c];
            rb[i] = *(const float4*)&W[(long)(n0 + row) * Ee + kb + c];
        }
    };
    auto stash = [&](int s) {
#pragma unroll
        for (int i = 0; i < 2; ++i) {
            const int v = tid + i * 256;
            const int row = v >> 2, c = (v & 3) * 4;
            uint32_t* pa = &sA[s][row * 20 + c];
            pa[0] = f2tf32(ra[i].x); pa[1] = f2tf32(ra[i].y);
            pa[2] = f2tf32(ra[i].z); pa[3] = f2tf32(ra[i].w);
            uint32_t* pb = &sB[s][row * 20 + c];
            pb[0] = f2tf32(rb[i].x); pb[1] = f2tf32(rb[i].y);
            pb[2] = f2tf32(rb[i].z); pb[3] = f2tf32(rb[i].w);
        }
    };
    auto compute = [&](int s) {
#pragma unroll
        for (int ks = 0; ks < 16; ks += 8) {
            uint32_t af[4][4], bf[4][2];
#pragma unroll
            for (int mt = 0; mt < 4; ++mt) {
                const uint32_t* p = &sA[s][(wm + mt * 16 + g) * 20 + ks + tg];
                af[mt][0] = p[0];
                af[mt][2] = p[4];
                af[mt][1] = p[160];   // +8 rows
                af[mt][3] = p[164];
            }
#pragma unroll
            for (int nt = 0; nt < 4; ++nt) {
                const uint32_t* p = &sB[s][(wn + nt * 8 + g) * 20 + ks + tg];
                bf[nt][0] = p[0];
                bf[nt][1] = p[4];
            }
#pragma unroll
            for (int mt = 0; mt < 4; ++mt)
#pragma unroll
                for (int nt = 0; nt < 4; ++nt) MMA_TF32(acc[mt][nt], af[mt], bf[nt]);
        }
    };

    fetch(0);
    stash(0);
    __syncthreads();

    for (int kt = 0; kt < Ee / 16; ++kt) {
        const int s = kt & 1;
        if (kt + 1 < Ee / 16) fetch(kt + 1);
        compute(s);
        if (kt + 1 < Ee / 16) stash(1 - s);
        __syncthreads();
    }

    // Epilogue: c0/c1 = row g, cols 2tg/2tg+1; c2/c3 = row g+8.
#pragma unroll
    for (int mt = 0; mt < 4; ++mt) {
#pragma unroll
        for (int i = 0; i < 2; ++i) {
            const int m = m0 + wm + mt * 16 + g + i * 8;
            const int b_ = m / Ss, srow = m % Ss;
#pragma unroll
            for (int nt = 0; nt < 4; ++nt) {
                const int n = n0 + wn + nt * 8 + tg * 2;
                float2 bv = *(const float2*)&bias[n];
                float2 r;
                r.x = acc[mt][nt][i * 2 + 0] + bv.x;
                r.y = acc[mt][nt][i * 2 + 1] + bv.y;
                if (HEAD_STORE) {
                    const int h = n >> 6, dd = n & 63;
                    *(float2*)&C[(((long)(b_ * Hh + h) * Ss + srow) * Dd) + dd] = r;
                } else {
                    *(float2*)&C[(long)m * Ee + n] = r;
                }
            }
        }
    }
}

// ---------------------------------------------------------------------------
// Fused attention (validated Round-1 version): fp32, 64-query tile per CTA.
// ---------------------------------------------------------------------------
__global__ __launch_bounds__(256) void attn_kernel(const int* __restrict__ mask,
                                                   const float* __restrict__ qh,
                                                   const float* __restrict__ kh,
                                                   const float* __restrict__ vh,
                                                   float* __restrict__ ctx) {
    extern __shared__ float sm[];
    float* Qt = sm;            // Qt[d*64 + r]
    float* Kt = sm + 4096;     // Kt[d*64 + c]
    float* Vs = sm + 8192;     // Vs[j*64 + d]
    float* Ps = sm + 12288;    // Ps[r*64 + j]

    const int tx = threadIdx.x;  // 0..15
    const int ty = threadIdx.y;  // 0..15
    const int tid = ty * 16 + tx;
    const int q0 = blockIdx.x * 64;
    const int bh = blockIdx.y;
    const int b = bh / Hh;
    const int h = bh % Hh;

    const float* Q = qh + (long)bh * Ss * Dd;
    const float* Kg = kh + (long)bh * Ss * Dd;
    const float* Vg = vh + (long)bh * Ss * Dd;
    const int* Mb = mask + (long)b * Ss * Ss;

    {
        const int r = tid >> 2;
        const int d0 = (tid & 3) << 4;
#pragma unroll
        for (int u = 0; u < 4; ++u) {
            float4 v = *(const float4*)&Q[(long)(q0 + r) * Dd + d0 + u * 4];
            Qt[(d0 + u * 4 + 0) * 64 + r] = v.x;
            Qt[(d0 + u * 4 + 1) * 64 + r] = v.y;
            Qt[(d0 + u * 4 + 2) * 64 + r] = v.z;
            Qt[(d0 + u * 4 + 3) * 64 + r] = v.w;
        }
    }

    float m_i[4], l_i[4], acc[4][4];
#pragma unroll
    for (int i = 0; i < 4; ++i) {
        m_i[i] = -1e30f;
        l_i[i] = 0.f;
#pragma unroll
        for (int j = 0; j < 4; ++j) acc[i][j] = 0.f;
    }

    const float scale = 0.125f;  // 1/sqrt(64)

    for (int k0 = 0; k0 < Ss; k0 += 64) {
        __syncthreads();
        {
            const int r = tid >> 2;
            const int d0 = (tid & 3) << 4;
#pragma unroll
            for (int u = 0; u < 4; ++u) {
                float4 kv = *(const float4*)&Kg[(long)(k0 + r) * Dd + d0 + u * 4];
                Kt[(d0 + u * 4 + 0) * 64 + r] = kv.x;
                Kt[(d0 + u * 4 + 1) * 64 + r] = kv.y;
                Kt[(d0 + u * 4 + 2) * 64 + r] = kv.z;
                Kt[(d0 + u * 4 + 3) * 64 + r] = kv.w;
                float4 vv = *(const float4*)&Vg[(long)(k0 + r) * Dd + d0 + u * 4];
                *(float4*)&Vs[r * 64 + d0 + u * 4] = vv;
            }
        }
        __syncthreads();

        float s[4][4];
#pragma unroll
        for (int i = 0; i < 4; ++i)
#pragma unroll
            for (int j = 0; j < 4; ++j) s[i][j] = 0.f;

#pragma unroll 16
        for (int d = 0; d < 64; ++d) {
            float4 a = *(const float4*)&Qt[d * 64 + (ty << 2)];
            float4 kk = *(const float4*)&Kt[d * 64 + (tx << 2)];
            s[0][0] += a.x * kk.x; s[0][1] += a.x * kk.y;
            s[0][2] += a.x * kk.z; s[0][3] += a.x * kk.w;
            s[1][0] += a.y * kk.x; s[1][1] += a.y * kk.y;
            s[1][2] += a.y * kk.z; s[1][3] += a.y * kk.w;
            s[2][0] += a.z * kk.x; s[2][1] += a.z * kk.y;
            s[2][2] += a.z * kk.z; s[2][3] += a.z * kk.w;
            s[3][0] += a.w * kk.x; s[3][1] += a.w * kk.y;
            s[3][2] += a.w * kk.z; s[3][3] += a.w * kk.w;
        }

#pragma unroll
        for (int i = 0; i < 4; ++i) {
            int4 mv = *(const int4*)&Mb[(long)(q0 + (ty << 2) + i) * Ss + k0 + (tx << 2)];
            s[i][0] = mv.x ? s[i][0] * scale : -1e10f;
            s[i][1] = mv.y ? s[i][1] * scale : -1e10f;
            s[i][2] = mv.z ? s[i][2] * scale : -1e10f;
            s[i][3] = mv.w ? s[i][3] * scale : -1e10f;

            float mx = fmaxf(fmaxf(s[i][0], s[i][1]), fmaxf(s[i][2], s[i][3]));
#pragma unroll
            for (int off = 8; off; off >>= 1)
                mx = fmaxf(mx, __shfl_xor_sync(0xffffffffu, mx, off));

            const float mnew = fmaxf(m_i[i], mx);
            const float alpha = __expf(m_i[i] - mnew);
            m_i[i] = mnew;

            float rs = 0.f;
#pragma unroll
            for (int j = 0; j < 4; ++j) {
                float p = __expf(s[i][j] - mnew);
                s[i][j] = p;
                rs += p;
            }
#pragma unroll
            for (int off = 8; off; off >>= 1)
                rs += __shfl_xor_sync(0xffffffffu, rs, off);

            l_i[i] = l_i[i] * alpha + rs;
#pragma unroll
            for (int j = 0; j < 4; ++j) acc[i][j] *= alpha;

            *(float4*)&Ps[((ty << 2) + i) * 64 + (tx << 2)] =
                make_float4(s[i][0], s[i][1], s[i][2], s[i][3]);
        }
        __syncthreads();

#pragma unroll 16
        for (int j = 0; j < 64; ++j) {
            float4 v = *(const float4*)&Vs[j * 64 + (tx << 2)];
            float p0 = Ps[((ty << 2) + 0) * 64 + j];
            float p1 = Ps[((ty << 2) + 1) * 64 + j];
            float p2 = Ps[((ty << 2) + 2) * 64 + j];
            float p3 = Ps[((ty << 2) + 3) * 64 + j];
            acc[0][0] += p0 * v.x; acc[0][1] += p0 * v.y;
            acc[0][2] += p0 * v.z; acc[0][3] += p0 * v.w;
            acc[1][0] += p1 * v.x; acc[1][1] += p1 * v.y;
            acc[1][2] += p1 * v.z; acc[1][3] += p1 * v.w;
            acc[2][0] += p2 * v.x; acc[2][1] += p2 * v.y;
            acc[2][2] += p2 * v.z; acc[2][3] += p2 * v.w;
            acc[3][0] += p3 * v.x; acc[3][1] += p3 * v.y;
            acc[3][2] += p3 * v.z; acc[3][3] += p3 * v.w;
        }
    }

#pragma unroll
    for (int i = 0; i < 4; ++i) {
        const float inv = 1.f / l_i[i];
        const int srow = q0 + (ty << 2) + i;
        float4 r = make_float4(acc[i][0] * inv, acc[i][1] * inv,
                               acc[i][2] * inv, acc[i][3] * inv);
        *(float4*)&g_ctx[((long)(b * Ss + srow)) * Ee + h * Dd + (tx << 2)] = r;
    }
    (void)ctx;
}

// ---------------------------------------------------------------------------
extern "C" void kernel_launch(void* const* d_in, const int* in_sizes, int n_in,
                              void* d_out, int out_size) {
    const float* q  = (const float*)d_in[0];
    const float* k  = (const float*)d_in[1];
    const float* v  = (const float*)d_in[2];
    const int* mask = (const int*)d_in[3];
    const float* Wq = (const float*)d_in[4];
    const float* bq = (const float*)d_in[5];
    const float* Wk = (const float*)d_in[6];
    const float* bk = (const float*)d_in[7];
    const float* Wv = (const float*)d_in[8];
    const float* bv = (const float*)d_in[9];
    const float* Wo = (const float*)d_in[10];
    const float* bo = (const float*)d_in[11];
    float* out = (float*)d_out;

    float *qh, *kh, *vh, *ctx;
    cudaGetSymbolAddress((void**)&qh, g_qh);
    cudaGetSymbolAddress((void**)&kh, g_kh);
    cudaGetSymbolAddress((void**)&vh, g_vh);
    cudaGetSymbolAddress((void**)&ctx, g_ctx);

    dim3 gg(Ee / 128, (Bb * Ss) / 128);  // 8 x 32
    gemm_mma<true><<<gg, 256>>>(q, Wq, bq, qh);
    gemm_mma<true><<<gg, 256>>>(k, Wk, bk, kh);
    gemm_mma<true><<<gg, 256>>>(v, Wv, bv, vh);

    cudaFuncSetAttribute(attn_kernel, cudaFuncAttributeMaxDynamicSharedMemorySize,
                         64 * 1024);
    dim3 blk(16, 16);
    dim3 gattn(Ss / 64, Bb * Hh);
    attn_kernel<<<gattn, blk, 64 * 1024>>>(mask, qh, kh, vh, ctx);

    gemm_mma<false><<<gg, 256>>>(ctx, Wo, bo, out);
}

// round 4
// speedup vs baseline: 2.7296x; 1.7890x over previous
#include <cuda_runtime.h>
#include <cstdint>

// Problem constants (MultiHeadAttention: B=2,S=2048,E=1024,H=16,D=64)
constexpr int Bb = 2;
constexpr int Ss = 2048;
constexpr int Ee = 1024;
constexpr int Hh = 16;
constexpr int Dd = 64;

// Scratch (device globals; no allocation allowed)
__device__ float g_qh[Bb * Hh * Ss * Dd];   // [B,H,S,D]
__device__ float g_kh[Bb * Hh * Ss * Dd];
__device__ float g_vh[Bb * Hh * Ss * Dd];
__device__ float g_ctx[Bb * Ss * Ee];       // [B,S,E]

__device__ __forceinline__ uint32_t f2tf32(float x) {
    uint32_t r;
    asm("cvt.rna.tf32.f32 %0, %1;" : "=r"(r) : "f"(x));
    return r;
}

#define MMA_TF32(c, a, b)                                                      \
    asm volatile(                                                              \
        "mma.sync.aligned.m16n8k8.row.col.f32.tf32.tf32.f32 "                  \
        "{%0,%1,%2,%3}, {%4,%5,%6,%7}, {%8,%9}, {%0,%1,%2,%3};"                \
        : "+f"((c)[0]), "+f"((c)[1]), "+f"((c)[2]), "+f"((c)[3])               \
        : "r"((a)[0]), "r"((a)[1]), "r"((a)[2]), "r"((a)[3]),                  \
          "r"((b)[0]), "r"((b)[1]))

// ---------------------------------------------------------------------------
// tf32 mma.sync GEMM (validated R3): C[m,n] = sum_k A[m,k]*W[n,k] + bias[n]
// ---------------------------------------------------------------------------
template <bool HEAD_STORE>
__global__ __launch_bounds__(256) void gemm_mma(const float* __restrict__ A,
                                                const float* __restrict__ W,
                                                const float* __restrict__ bias,
                                                float* __restrict__ C) {
    __shared__ uint32_t sA[2][128 * 20];
    __shared__ uint32_t sB[2][128 * 20];

    const int tid = threadIdx.x;
    const int lane = tid & 31;
    const int g = lane >> 2, tg = lane & 3;
    const int w = tid >> 5;
    const int wm = (w >> 2) * 64;
    const int wn = (w & 3) * 32;
    const int m0 = blockIdx.y * 128, n0 = blockIdx.x * 128;

    float acc[4][4][4];
#pragma unroll
    for (int mt = 0; mt < 4; ++mt)
#pragma unroll
        for (int nt = 0; nt < 4; ++nt)
#pragma unroll
            for (int i = 0; i < 4; ++i) acc[mt][nt][i] = 0.f;

    float4 ra[2], rb[2];

    auto fetch = [&](int kt) {
        const int kb = kt * 16;
#pragma unroll
        for (int i = 0; i < 2; ++i) {
            const int v = tid + i * 256;
            const int row = v >> 2, c = (v & 3) * 4;
            ra[i] = *(const float4*)&A[(long)(m0 + row) * Ee + kb + c];
            rb[i] = *(const float4*)&W[(long)(n0 + row) * Ee + kb + c];
        }
    };
    auto stash = [&](int s) {
#pragma unroll
        for (int i = 0; i < 2; ++i) {
            const int v = tid + i * 256;
            const int row = v >> 2, c = (v & 3) * 4;
            uint32_t* pa = &sA[s][row * 20 + c];
            pa[0] = f2tf32(ra[i].x); pa[1] = f2tf32(ra[i].y);
            pa[2] = f2tf32(ra[i].z); pa[3] = f2tf32(ra[i].w);
            uint32_t* pb = &sB[s][row * 20 + c];
            pb[0] = f2tf32(rb[i].x); pb[1] = f2tf32(rb[i].y);
            pb[2] = f2tf32(rb[i].z); pb[3] = f2tf32(rb[i].w);
        }
    };
    auto compute = [&](int s) {
#pragma unroll
        for (int ks = 0; ks < 16; ks += 8) {
            uint32_t af[4][4], bf[4][2];
#pragma unroll
            for (int mt = 0; mt < 4; ++mt) {
                const uint32_t* p = &sA[s][(wm + mt * 16 + g) * 20 + ks + tg];
                af[mt][0] = p[0];
                af[mt][2] = p[4];
                af[mt][1] = p[160];
                af[mt][3] = p[164];
            }
#pragma unroll
            for (int nt = 0; nt < 4; ++nt) {
                const uint32_t* p = &sB[s][(wn + nt * 8 + g) * 20 + ks + tg];
                bf[nt][0] = p[0];
                bf[nt][1] = p[4];
            }
#pragma unroll
            for (int mt = 0; mt < 4; ++mt)
#pragma unroll
                for (int nt = 0; nt < 4; ++nt) MMA_TF32(acc[mt][nt], af[mt], bf[nt]);
        }
    };

    fetch(0);
    stash(0);
    __syncthreads();

    for (int kt = 0; kt < Ee / 16; ++kt) {
        const int s = kt & 1;
        if (kt + 1 < Ee / 16) fetch(kt + 1);
        compute(s);
        if (kt + 1 < Ee / 16) stash(1 - s);
        __syncthreads();
    }

#pragma unroll
    for (int mt = 0; mt < 4; ++mt) {
#pragma unroll
        for (int i = 0; i < 2; ++i) {
            const int m = m0 + wm + mt * 16 + g + i * 8;
            const int b_ = m / Ss, srow = m % Ss;
#pragma unroll
            for (int nt = 0; nt < 4; ++nt) {
                const int n = n0 + wn + nt * 8 + tg * 2;
                float2 bv = *(const float2*)&bias[n];
                float2 r;
                r.x = acc[mt][nt][i * 2 + 0] + bv.x;
                r.y = acc[mt][nt][i * 2 + 1] + bv.y;
                if (HEAD_STORE) {
                    const int h = n >> 6, dd = n & 63;
                    *(float2*)&C[(((long)(b_ * Hh + h) * Ss + srow) * Dd) + dd] = r;
                } else {
                    *(float2*)&C[(long)m * Ee + n] = r;
                }
            }
        }
    }
}

// ---------------------------------------------------------------------------
// Tensor-core flash attention: CTA = 128 queries x full key sweep (64-key tiles)
// 8 warps; warp w owns query rows [w*16, w*16+16) for the whole kernel.
// smem (dynamic, uint32): Ks[64][68] (K tile, [key][d], tf32)
//                         Vt[64][68] (V tile transposed, [d][key], tf32)
//                         Ps[128][68] (P round-trip, [qrow][key], tf32)
// ---------------------------------------------------------------------------
__global__ __launch_bounds__(256) void attn_mma(const int* __restrict__ mask,
                                                const float* __restrict__ qh,
                                                const float* __restrict__ kh,
                                                const float* __restrict__ vh,
                                                float* __restrict__ ctx) {
    extern __shared__ uint32_t dsm[];
    uint32_t* Ks = dsm;               // 64*68
    uint32_t* Vt = dsm + 64 * 68;     // 64*68
    uint32_t* Ps = dsm + 128 * 68;    // 128*68

    const int tid = threadIdx.x;
    const int lane = tid & 31;
    const int g = lane >> 2, tg = lane & 3;
    const int w = tid >> 5;
    const int q0 = blockIdx.x * 128;
    const int bh = blockIdx.y;
    const int b = bh / Hh;
    const int h = bh % Hh;

    const float* Q = qh + (long)bh * Ss * Dd;
    const float* Kg = kh + (long)bh * Ss * Dd;
    const float* Vg = vh + (long)bh * Ss * Dd;
    const int* Mb = mask + (long)b * Ss * Ss;

    // Q fragments for rows r0=q0+w*16+g and r0+8, held all kernel (tf32)
    const int r0 = q0 + w * 16 + g;
    uint32_t qf[8][4];
#pragma unroll
    for (int ks = 0; ks < 8; ++ks) {
        qf[ks][0] = f2tf32(Q[(long)r0 * Dd + ks * 8 + tg]);
        qf[ks][1] = f2tf32(Q[(long)(r0 + 8) * Dd + ks * 8 + tg]);
        qf[ks][2] = f2tf32(Q[(long)r0 * Dd + ks * 8 + tg + 4]);
        qf[ks][3] = f2tf32(Q[(long)(r0 + 8) * Dd + ks * 8 + tg + 4]);
    }

    float oacc[8][4];
#pragma unroll
    for (int nt = 0; nt < 8; ++nt)
#pragma unroll
        for (int i = 0; i < 4; ++i) oacc[nt][i] = 0.f;
    float mrow[2] = {-1e30f, -1e30f};
    float lrow[2] = {0.f, 0.f};

    for (int kt = 0; kt < Ss / 64; ++kt) {
        __syncthreads();  // Ks/Vt safe to overwrite (all warps past PV)
        // Stage K tile [key][d] and V tile transposed [d][key], tf32
        {
            const int r = tid >> 2;          // 0..63 key row
            const int c0 = (tid & 3) * 16;   // d offset
#pragma unroll
            for (int u = 0; u < 4; ++u) {
                const int c = c0 + u * 4;
                float4 kv = *(const float4*)&Kg[(long)(kt * 64 + r) * Dd + c];
                *(uint4*)&Ks[r * 68 + c] =
                    make_uint4(f2tf32(kv.x), f2tf32(kv.y), f2tf32(kv.z), f2tf32(kv.w));
                float4 vv = *(const float4*)&Vg[(long)(kt * 64 + r) * Dd + c];
                Vt[(c + 0) * 68 + r] = f2tf32(vv.x);
                Vt[(c + 1) * 68 + r] = f2tf32(vv.y);
                Vt[(c + 2) * 68 + r] = f2tf32(vv.z);
                Vt[(c + 3) * 68 + r] = f2tf32(vv.w);
            }
        }
        __syncthreads();

        // QK^T: s[nt] covers keys nt*8..+8, rows r0 / r0+8
        float s[8][4];
#pragma unroll
        for (int nt = 0; nt < 8; ++nt)
#pragma unroll
            for (int i = 0; i < 4; ++i) s[nt][i] = 0.f;
#pragma unroll
        for (int ks = 0; ks < 8; ++ks) {
#pragma unroll
            for (int nt = 0; nt < 8; ++nt) {
                uint32_t bf[2];
                const uint32_t* p = &Ks[(nt * 8 + g) * 68 + ks * 8 + tg];
                bf[0] = p[0];
                bf[1] = p[4];
                MMA_TF32(s[nt], qf[ks], bf);
            }
        }

        // Mask + online softmax per row (i=0: row r0, i=1: row r0+8)
#pragma unroll
        for (int i = 0; i < 2; ++i) {
            const int row = r0 + i * 8;
            float rmax = -1e30f;
#pragma unroll
            for (int nt = 0; nt < 8; ++nt) {
                int2 mv = *(const int2*)&Mb[(long)row * Ss + kt * 64 + nt * 8 + tg * 2];
                float a = mv.x ? s[nt][i * 2 + 0] * 0.125f : -1e10f;
                float c = mv.y ? s[nt][i * 2 + 1] * 0.125f : -1e10f;
                s[nt][i * 2 + 0] = a;
                s[nt][i * 2 + 1] = c;
                rmax = fmaxf(rmax, fmaxf(a, c));
            }
            rmax = fmaxf(rmax, __shfl_xor_sync(0xffffffffu, rmax, 1));
            rmax = fmaxf(rmax, __shfl_xor_sync(0xffffffffu, rmax, 2));

            const float mnew = fmaxf(mrow[i], rmax);
            const float alpha = __expf(mrow[i] - mnew);
            mrow[i] = mnew;

            float rsum = 0.f;
#pragma unroll
            for (int nt = 0; nt < 8; ++nt) {
                float a = __expf(s[nt][i * 2 + 0] - mnew);
                float c = __expf(s[nt][i * 2 + 1] - mnew);
                s[nt][i * 2 + 0] = a;
                s[nt][i * 2 + 1] = c;
                rsum += a + c;
            }
            rsum += __shfl_xor_sync(0xffffffffu, rsum, 1);
            rsum += __shfl_xor_sync(0xffffffffu, rsum, 2);
            lrow[i] = lrow[i] * alpha + rsum;

#pragma unroll
            for (int nt = 0; nt < 8; ++nt) {
                oacc[nt][i * 2 + 0] *= alpha;
                oacc[nt][i * 2 + 1] *= alpha;
                // stash P (tf32) for layout conversion
                uint32_t* pp = &Ps[(w * 16 + g + i * 8) * 68 + nt * 8 + tg * 2];
                pp[0] = f2tf32(s[nt][i * 2 + 0]);
                pp[1] = f2tf32(s[nt][i * 2 + 1]);
            }
        }
        __syncwarp();  // own-warp rows only: warp-local store->load

        // PV: oacc[nt] += P[16 x 64keys] * Vt[d nt*8..][keys]
#pragma unroll
        for (int ks = 0; ks < 8; ++ks) {
            uint32_t pf[4];
            const uint32_t* pp = &Ps[(w * 16 + g) * 68 + ks * 8 + tg];
            pf[0] = pp[0];
            pf[2] = pp[4];
            pf[1] = pp[8 * 68];      // row +8
            pf[3] = pp[8 * 68 + 4];
#pragma unroll
            for (int nt = 0; nt < 8; ++nt) {
                uint32_t bf[2];
                const uint32_t* vp = &Vt[(nt * 8 + g) * 68 + ks * 8 + tg];
                bf[0] = vp[0];
                bf[1] = vp[4];
                MMA_TF32(oacc[nt], pf, bf);
            }
        }
    }

    // Epilogue: normalize, store ctx [B,S,E] at cols h*64 + d
#pragma unroll
    for (int i = 0; i < 2; ++i) {
        const float inv = 1.f / lrow[i];
        const int row = r0 + i * 8;
#pragma unroll
        for (int nt = 0; nt < 8; ++nt) {
            float2 r;
            r.x = oacc[nt][i * 2 + 0] * inv;
            r.y = oacc[nt][i * 2 + 1] * inv;
            *(float2*)&g_ctx[((long)(b * Ss + row)) * Ee + h * Dd + nt * 8 + tg * 2] = r;
        }
    }
    (void)ctx;
}

// ---------------------------------------------------------------------------
extern "C" void kernel_launch(void* const* d_in, const int* in_sizes, int n_in,
                              void* d_out, int out_size) {
    const float* q  = (const float*)d_in[0];
    const float* k  = (const float*)d_in[1];
    const float* v  = (const float*)d_in[2];
    const int* mask = (const int*)d_in[3];
    const float* Wq = (const float*)d_in[4];
    const float* bq = (const float*)d_in[5];
    const float* Wk = (const float*)d_in[6];
    const float* bk = (const float*)d_in[7];
    const float* Wv = (const float*)d_in[8];
    const float* bv = (const float*)d_in[9];
    const float* Wo = (const float*)d_in[10];
    const float* bo = (const float*)d_in[11];
    float* out = (float*)d_out;

    float *qh, *kh, *vh, *ctx;
    cudaGetSymbolAddress((void**)&qh, g_qh);
    cudaGetSymbolAddress((void**)&kh, g_kh);
    cudaGetSymbolAddress((void**)&vh, g_vh);
    cudaGetSymbolAddress((void**)&ctx, g_ctx);

    dim3 gg(Ee / 128, (Bb * Ss) / 128);  // 8 x 32
    gemm_mma<true><<<gg, 256>>>(q, Wq, bq, qh);
    gemm_mma<true><<<gg, 256>>>(k, Wk, bk, kh);
    gemm_mma<true><<<gg, 256>>>(v, Wv, bv, vh);

    const int ATTN_SMEM = 256 * 68 * 4;  // 69632 B
    cudaFuncSetAttribute(attn_mma, cudaFuncAttributeMaxDynamicSharedMemorySize,
                         ATTN_SMEM);
    dim3 gattn(Ss / 128, Bb * Hh);  // 16 x 32
    attn_mma<<<gattn, 256, ATTN_SMEM>>>(mask, qh, kh, vh, ctx);

    gemm_mma<false><<<gg, 256>>>(ctx, Wo, bo, out);
}

// round 5
// speedup vs baseline: 2.8036x; 1.0271x over previous
#include <cuda_runtime.h>
#include <cstdint>

// Problem constants (MultiHeadAttention: B=2,S=2048,E=1024,H=16,D=64)
constexpr int Bb = 2;
constexpr int Ss = 2048;
constexpr int Ee = 1024;
constexpr int Hh = 16;
constexpr int Dd = 64;

// Scratch (device globals; no allocation allowed)
__device__ float g_qh[Bb * Hh * Ss * Dd];   // [B,H,S,D]
__device__ float g_kh[Bb * Hh * Ss * Dd];
__device__ float g_vh[Bb * Hh * Ss * Dd];
__device__ float g_ctx[Bb * Ss * Ee];       // [B,S,E]

__device__ __forceinline__ uint32_t f2tf32(float x) {
    uint32_t r;
    asm("cvt.rna.tf32.f32 %0, %1;" : "=r"(r) : "f"(x));
    return r;
}

#define MMA_TF32(c, a, b)                                                      \
    asm volatile(                                                              \
        "mma.sync.aligned.m16n8k8.row.col.f32.tf32.tf32.f32 "                  \
        "{%0,%1,%2,%3}, {%4,%5,%6,%7}, {%8,%9}, {%0,%1,%2,%3};"                \
        : "+f"((c)[0]), "+f"((c)[1]), "+f"((c)[2]), "+f"((c)[3])               \
        : "r"((a)[0]), "r"((a)[1]), "r"((a)[2]), "r"((a)[3]),                  \
          "r"((b)[0]), "r"((b)[1]))

// ---------------------------------------------------------------------------
// tf32 mma.sync GEMM (validated R3/R4): C[m,n] = sum_k A[m,k]*W[n,k] + bias[n]
// ---------------------------------------------------------------------------
template <bool HEAD_STORE>
__global__ __launch_bounds__(256) void gemm_mma(const float* __restrict__ A,
                                                const float* __restrict__ W,
                                                const float* __restrict__ bias,
                                                float* __restrict__ C) {
    __shared__ uint32_t sA[2][128 * 20];
    __shared__ uint32_t sB[2][128 * 20];

    const int tid = threadIdx.x;
    const int lane = tid & 31;
    const int g = lane >> 2, tg = lane & 3;
    const int w = tid >> 5;
    const int wm = (w >> 2) * 64;
    const int wn = (w & 3) * 32;
    const int m0 = blockIdx.y * 128, n0 = blockIdx.x * 128;

    float acc[4][4][4];
#pragma unroll
    for (int mt = 0; mt < 4; ++mt)
#pragma unroll
        for (int nt = 0; nt < 4; ++nt)
#pragma unroll
            for (int i = 0; i < 4; ++i) acc[mt][nt][i] = 0.f;

    float4 ra[2], rb[2];

    auto fetch = [&](int kt) {
        const int kb = kt * 16;
#pragma unroll
        for (int i = 0; i < 2; ++i) {
            const int v = tid + i * 256;
            const int row = v >> 2, c = (v & 3) * 4;
            ra[i] = *(const float4*)&A[(long)(m0 + row) * Ee + kb + c];
            rb[i] = *(const float4*)&W[(long)(n0 + row) * Ee + kb + c];
        }
    };
    auto stash = [&](int s) {
#pragma unroll
        for (int i = 0; i < 2; ++i) {
            const int v = tid + i * 256;
            const int row = v >> 2, c = (v & 3) * 4;
            uint32_t* pa = &sA[s][row * 20 + c];
            pa[0] = f2tf32(ra[i].x); pa[1] = f2tf32(ra[i].y);
            pa[2] = f2tf32(ra[i].z); pa[3] = f2tf32(ra[i].w);
            uint32_t* pb = &sB[s][row * 20 + c];
            pb[0] = f2tf32(rb[i].x); pb[1] = f2tf32(rb[i].y);
            pb[2] = f2tf32(rb[i].z); pb[3] = f2tf32(rb[i].w);
        }
    };
    auto compute = [&](int s) {
#pragma unroll
        for (int ks = 0; ks < 16; ks += 8) {
            uint32_t af[4][4], bf[4][2];
#pragma unroll
            for (int mt = 0; mt < 4; ++mt) {
                const uint32_t* p = &sA[s][(wm + mt * 16 + g) * 20 + ks + tg];
                af[mt][0] = p[0];
                af[mt][2] = p[4];
                af[mt][1] = p[160];
                af[mt][3] = p[164];
            }
#pragma unroll
            for (int nt = 0; nt < 4; ++nt) {
                const uint32_t* p = &sB[s][(wn + nt * 8 + g) * 20 + ks + tg];
                bf[nt][0] = p[0];
                bf[nt][1] = p[4];
            }
#pragma unroll
            for (int mt = 0; mt < 4; ++mt)
#pragma unroll
                for (int nt = 0; nt < 4; ++nt) MMA_TF32(acc[mt][nt], af[mt], bf[nt]);
        }
    };

    fetch(0);
    stash(0);
    __syncthreads();

    for (int kt = 0; kt < Ee / 16; ++kt) {
        const int s = kt & 1;
        if (kt + 1 < Ee / 16) fetch(kt + 1);
        compute(s);
        if (kt + 1 < Ee / 16) stash(1 - s);
        __syncthreads();
    }

#pragma unroll
    for (int mt = 0; mt < 4; ++mt) {
#pragma unroll
        for (int i = 0; i < 2; ++i) {
            const int m = m0 + wm + mt * 16 + g + i * 8;
            const int b_ = m / Ss, srow = m % Ss;
#pragma unroll
            for (int nt = 0; nt < 4; ++nt) {
                const int n = n0 + wn + nt * 8 + tg * 2;
                float2 bv = *(const float2*)&bias[n];
                float2 r;
                r.x = acc[mt][nt][i * 2 + 0] + bv.x;
                r.y = acc[mt][nt][i * 2 + 1] + bv.y;
                if (HEAD_STORE) {
                    const int h = n >> 6, dd = n & 63;
                    *(float2*)&C[(((long)(b_ * Hh + h) * Ss + srow) * Dd) + dd] = r;
                } else {
                    *(float2*)&C[(long)m * Ee + n] = r;
                }
            }
        }
    }
}

// ---------------------------------------------------------------------------
// Tensor-core flash attention (R5):
//  - mask hoisted to tile top, bit-compressed into 2 regs
//  - Vt / Ps use pair-permuted layout (cols c,c+4 adjacent), stride 72 words,
//    so PV fragment loads are conflict-free LDS.64
// smem words: Ks[64][68] @0, Vt[64][72] @4352, Ps[128][72] @8960 (tot 18176)
// ---------------------------------------------------------------------------
__global__ __launch_bounds__(256, 2) void attn_mma(const int* __restrict__ mask,
                                                   const float* __restrict__ qh,
                                                   const float* __restrict__ kh,
                                                   const float* __restrict__ vh,
                                                   float* __restrict__ ctx) {
    extern __shared__ uint32_t dsm[];
    uint32_t* Ks = dsm;                // stride 68
    uint32_t* Vt = dsm + 64 * 68;      // stride 72, permuted cols
    uint32_t* Ps = dsm + 64 * 68 + 64 * 72;  // stride 72, permuted cols

    const int tid = threadIdx.x;
    const int lane = tid & 31;
    const int g = lane >> 2, tg = lane & 3;
    const int w = tid >> 5;
    const int q0 = blockIdx.x * 128;
    const int bh = blockIdx.y;
    const int b = bh / Hh;
    const int h = bh % Hh;

    const float* Q = qh + (long)bh * Ss * Dd;
    const float* Kg = kh + (long)bh * Ss * Dd;
    const float* Vg = vh + (long)bh * Ss * Dd;
    const int* Mb = mask + (long)b * Ss * Ss;

    // Q fragments for rows r0=q0+w*16+g and r0+8, held all kernel (tf32)
    const int r0 = q0 + w * 16 + g;
    uint32_t qf[8][4];
#pragma unroll
    for (int ks = 0; ks < 8; ++ks) {
        qf[ks][0] = f2tf32(Q[(long)r0 * Dd + ks * 8 + tg]);
        qf[ks][1] = f2tf32(Q[(long)(r0 + 8) * Dd + ks * 8 + tg]);
        qf[ks][2] = f2tf32(Q[(long)r0 * Dd + ks * 8 + tg + 4]);
        qf[ks][3] = f2tf32(Q[(long)(r0 + 8) * Dd + ks * 8 + tg + 4]);
    }

    // Ps stash offsets for cols 2tg / 2tg+1 within an 8-col permuted group
    const int po0 = (((2 * tg) & 3) << 1) | ((2 * tg) >> 2);
    const int po1 = (((2 * tg + 1) & 3) << 1) | ((2 * tg + 1) >> 2);

    float oacc[8][4];
#pragma unroll
    for (int nt = 0; nt < 8; ++nt)
#pragma unroll
        for (int i = 0; i < 4; ++i) oacc[nt][i] = 0.f;
    float mrow[2] = {-1e30f, -1e30f};
    float lrow[2] = {0.f, 0.f};

    for (int kt = 0; kt < Ss / 64; ++kt) {
        __syncthreads();  // Ks/Vt/Ps safe to overwrite
        // Stage K tile [key][d] (stride 68) and V transposed [d][key] permuted
        {
            const int r = tid >> 2;          // 0..63 key row
            const int c0 = (tid & 3) * 16;   // d offset
            const int koff = (r >> 3) * 8 + ((r & 3) << 1) + ((r >> 2) & 1);
#pragma unroll
            for (int u = 0; u < 4; ++u) {
                const int c = c0 + u * 4;
                float4 kv = *(const float4*)&Kg[(long)(kt * 64 + r) * Dd + c];
                *(uint4*)&Ks[r * 68 + c] =
                    make_uint4(f2tf32(kv.x), f2tf32(kv.y), f2tf32(kv.z), f2tf32(kv.w));
                float4 vv = *(const float4*)&Vg[(long)(kt * 64 + r) * Dd + c];
                Vt[(c + 0) * 72 + koff] = f2tf32(vv.x);
                Vt[(c + 1) * 72 + koff] = f2tf32(vv.y);
                Vt[(c + 2) * 72 + koff] = f2tf32(vv.z);
                Vt[(c + 3) * 72 + koff] = f2tf32(vv.w);
            }
        }

        // Hoisted mask loads -> 2x16-bit fields (overlaps staging + QK MMAs)
        uint32_t mbits[2] = {0u, 0u};
#pragma unroll
        for (int i = 0; i < 2; ++i) {
            const int row = r0 + i * 8;
#pragma unroll
            for (int nt = 0; nt < 8; ++nt) {
                int2 mv = *(const int2*)&Mb[(long)row * Ss + kt * 64 + nt * 8 + tg * 2];
                mbits[i] |= (mv.x ? 1u : 0u) << (2 * nt);
                mbits[i] |= (mv.y ? 1u : 0u) << (2 * nt + 1);
            }
        }
        __syncthreads();

        // QK^T: s[nt] covers keys nt*8..+8, rows r0 / r0+8
        float s[8][4];
#pragma unroll
        for (int nt = 0; nt < 8; ++nt)
#pragma unroll
            for (int i = 0; i < 4; ++i) s[nt][i] = 0.f;
#pragma unroll
        for (int ks = 0; ks < 8; ++ks) {
#pragma unroll
            for (int nt = 0; nt < 8; ++nt) {
                uint32_t bf[2];
                const uint32_t* p = &Ks[(nt * 8 + g) * 68 + ks * 8 + tg];
                bf[0] = p[0];
                bf[1] = p[4];
                MMA_TF32(s[nt], qf[ks], bf);
            }
        }

        // Mask (from mbits) + online softmax per row
#pragma unroll
        for (int i = 0; i < 2; ++i) {
            float rmax = -1e30f;
#pragma unroll
            for (int nt = 0; nt < 8; ++nt) {
                float a = ((mbits[i] >> (2 * nt)) & 1u) ? s[nt][i * 2 + 0] * 0.125f
                                                        : -1e10f;
                float c = ((mbits[i] >> (2 * nt + 1)) & 1u) ? s[nt][i * 2 + 1] * 0.125f
                                                            : -1e10f;
                s[nt][i * 2 + 0] = a;
                s[nt][i * 2 + 1] = c;
                rmax = fmaxf(rmax, fmaxf(a, c));
            }
            rmax = fmaxf(rmax, __shfl_xor_sync(0xffffffffu, rmax, 1));
            rmax = fmaxf(rmax, __shfl_xor_sync(0xffffffffu, rmax, 2));

            const float mnew = fmaxf(mrow[i], rmax);
            const float alpha = __expf(mrow[i] - mnew);
            mrow[i] = mnew;

            float rsum = 0.f;
#pragma unroll
            for (int nt = 0; nt < 8; ++nt) {
                float a = __expf(s[nt][i * 2 + 0] - mnew);
                float c = __expf(s[nt][i * 2 + 1] - mnew);
                s[nt][i * 2 + 0] = a;
                s[nt][i * 2 + 1] = c;
                rsum += a + c;
            }
            rsum += __shfl_xor_sync(0xffffffffu, rsum, 1);
            rsum += __shfl_xor_sync(0xffffffffu, rsum, 2);
            lrow[i] = lrow[i] * alpha + rsum;

#pragma unroll
            for (int nt = 0; nt < 8; ++nt) {
                oacc[nt][i * 2 + 0] *= alpha;
                oacc[nt][i * 2 + 1] *= alpha;
                uint32_t* pp = &Ps[(w * 16 + g + i * 8) * 72 + nt * 8];
                pp[po0] = f2tf32(s[nt][i * 2 + 0]);
                pp[po1] = f2tf32(s[nt][i * 2 + 1]);
            }
        }
        __syncwarp();  // own-warp rows only: warp-local store->load

        // PV with LDS.64 fragments (permuted pair layout)
#pragma unroll
        for (int ks = 0; ks < 8; ++ks) {
            uint32_t pf[4];
            {
                uint2 lo = *(const uint2*)&Ps[(w * 16 + g) * 72 + ks * 8 + 2 * tg];
                uint2 hi = *(const uint2*)&Ps[(w * 16 + g + 8) * 72 + ks * 8 + 2 * tg];
                pf[0] = lo.x;  // (row g,   col tg)
                pf[2] = lo.y;  // (row g,   col tg+4)
                pf[1] = hi.x;  // (row g+8, col tg)
                pf[3] = hi.y;  // (row g+8, col tg+4)
            }
#pragma unroll
            for (int nt = 0; nt < 8; ++nt) {
                uint2 bv = *(const uint2*)&Vt[(nt * 8 + g) * 72 + ks * 8 + 2 * tg];
                uint32_t bf[2] = {bv.x, bv.y};
                MMA_TF32(oacc[nt], pf, bf);
            }
        }
    }

    // Epilogue: normalize, store ctx [B,S,E] at cols h*64 + d
#pragma unroll
    for (int i = 0; i < 2; ++i) {
        const float inv = 1.f / lrow[i];
        const int row = r0 + i * 8;
#pragma unroll
        for (int nt = 0; nt < 8; ++nt) {
            float2 r;
            r.x = oacc[nt][i * 2 + 0] * inv;
            r.y = oacc[nt][i * 2 + 1] * inv;
            *(float2*)&g_ctx[((long)(b * Ss + row)) * Ee + h * Dd + nt * 8 + tg * 2] = r;
        }
    }
    (void)ctx;
}

// ---------------------------------------------------------------------------
extern "C" void kernel_launch(void* const* d_in, const int* in_sizes, int n_in,
                              void* d_out, int out_size) {
    const float* q  = (const float*)d_in[0];
    const float* k  = (const float*)d_in[1];
    const float* v  = (const float*)d_in[2];
    const int* mask = (const int*)d_in[3];
    const float* Wq = (const float*)d_in[4];
    const float* bq = (const float*)d_in[5];
    const float* Wk = (const float*)d_in[6];
    const float* bk = (const float*)d_in[7];
    const float* Wv = (const float*)d_in[8];
    const float* bv = (const float*)d_in[9];
    const float* Wo = (const float*)d_in[10];
    const float* bo = (const float*)d_in[11];
    float* out = (float*)d_out;

    float *qh, *kh, *vh, *ctx;
    cudaGetSymbolAddress((void**)&qh, g_qh);
    cudaGetSymbolAddress((void**)&kh, g_kh);
    cudaGetSymbolAddress((void**)&vh, g_vh);
    cudaGetSymbolAddress((void**)&ctx, g_ctx);

    dim3 gg(Ee / 128, (Bb * Ss) / 128);  // 8 x 32
    gemm_mma<true><<<gg, 256>>>(q, Wq, bq, qh);
    gemm_mma<true><<<gg, 256>>>(k, Wk, bk, kh);
    gemm_mma<true><<<gg, 256>>>(v, Wv, bv, vh);

    const int ATTN_SMEM = (64 * 68 + 64 * 72 + 128 * 72) * 4;  // 72704 B
    cudaFuncSetAttribute(attn_mma, cudaFuncAttributeMaxDynamicSharedMemorySize,
                         ATTN_SMEM);
    dim3 gattn(Ss / 128, Bb * Hh);  // 16 x 32
    attn_mma<<<gattn, 256, ATTN_SMEM>>>(mask, qh, kh, vh, ctx);

    gemm_mma<false><<<gg, 256>>>(ctx, Wo, bo, out);
}

// round 6
// speedup vs baseline: 2.9364x; 1.0474x over previous
#include <cuda_runtime.h>
#include <cstdint>

// Problem constants (MultiHeadAttention: B=2,S=2048,E=1024,H=16,D=64)
constexpr int Bb = 2;
constexpr int Ss = 2048;
constexpr int Ee = 1024;
constexpr int Hh = 16;
constexpr int Dd = 64;

// Scratch (device globals; no allocation allowed)
__device__ float g_qh[Bb * Hh * Ss * Dd];   // [B,H,S,D]
__device__ float g_kh[Bb * Hh * Ss * Dd];
__device__ float g_vh[Bb * Hh * Ss * Dd];
__device__ float g_ctx[Bb * Ss * Ee];       // [B,S,E]
__device__ uint32_t g_mbits[Bb * Ss * Ss / 32];  // permuted mask bits

__device__ __forceinline__ uint32_t f2tf32(float x) {
    uint32_t r;
    asm("cvt.rna.tf32.f32 %0, %1;" : "=r"(r) : "f"(x));
    return r;
}

#define MMA_TF32(c, a, b)                                                      \
    asm volatile(                                                              \
        "mma.sync.aligned.m16n8k8.row.col.f32.tf32.tf32.f32 "                  \
        "{%0,%1,%2,%3}, {%4,%5,%6,%7}, {%8,%9}, {%0,%1,%2,%3};"                \
        : "+f"((c)[0]), "+f"((c)[1]), "+f"((c)[2]), "+f"((c)[3])               \
        : "r"((a)[0]), "r"((a)[1]), "r"((a)[2]), "r"((a)[3]),                  \
          "r"((b)[0]), "r"((b)[1]))

// ---------------------------------------------------------------------------
// Mask bit-compression. Thread -> (row=b*S+s, key-tile kt, half h).
// Bit layout per (row, kt) 64-bit word pair: bit (32h + 16*(u>>1) + 2nt + (u&1))
// = mask[row][kt*64 + nt*8 + 4h + u], so attn lane tg reads a contiguous
// 16-bit field: word (tg>>1), shift (tg&1)*16.
// ---------------------------------------------------------------------------
__global__ __launch_bounds__(256) void mask_compress(const int* __restrict__ mask,
                                                     uint32_t* __restrict__ out) {
    const int idx = blockIdx.x * 256 + threadIdx.x;  // B*S*32*2 = 262144
    const int h = idx & 1;
    const int kt = (idx >> 1) & 31;
    const int br = idx >> 6;
    const int* p = mask + (long)br * Ss + kt * 64 + 4 * h;
    uint32_t bits = 0;
#pragma unroll
    for (int nt = 0; nt < 8; ++nt) {
        int4 m = *(const int4*)&p[nt * 8];
        bits |= (m.x ? 1u : 0u) << (2 * nt);
        bits |= (m.y ? 1u : 0u) << (2 * nt + 1);
        bits |= (m.z ? 1u : 0u) << (16 + 2 * nt);
        bits |= (m.w ? 1u : 0u) << (16 + 2 * nt + 1);
    }
    out[idx] = bits;
}

// ---------------------------------------------------------------------------
// tf32 mma.sync GEMM: C[m,n] = sum_k A[m,k]*W[n,k] + bias[n]
// R6: pair-permuted smem layout (k and k+4 adjacent), stride 24 words ->
// all fragment loads are conflict-free LDS.64. 48KB static smem.
// ---------------------------------------------------------------------------
template <bool HEAD_STORE>
__global__ __launch_bounds__(256) void gemm_mma(const float* __restrict__ A,
                                                const float* __restrict__ W,
                                                const float* __restrict__ bias,
                                                float* __restrict__ C) {
    __shared__ uint32_t gsm[12288];  // [sA0|sB0|sA1|sB1], 3072 words each

    const int tid = threadIdx.x;
    const int lane = tid & 31;
    const int g = lane >> 2, tg = lane & 3;
    const int w = tid >> 5;
    const int wm = (w >> 2) * 64;
    const int wn = (w & 3) * 32;
    const int m0 = blockIdx.y * 128, n0 = blockIdx.x * 128;

    float acc[4][4][4];
#pragma unroll
    for (int mt = 0; mt < 4; ++mt)
#pragma unroll
        for (int nt = 0; nt < 4; ++nt)
#pragma unroll
            for (int i = 0; i < 4; ++i) acc[mt][nt][i] = 0.f;

    float4 ra[2], rb[2];

    auto fetch = [&](int kt) {
        const int kb = kt * 16;
#pragma unroll
        for (int i = 0; i < 2; ++i) {
            const int v = tid + i * 256;
            const int row = v >> 2, c = (v & 3) * 4;
            ra[i] = *(const float4*)&A[(long)(m0 + row) * Ee + kb + c];
            rb[i] = *(const float4*)&W[(long)(n0 + row) * Ee + kb + c];
        }
    };
    // permuted store: element k -> (k&8) + 2*(k&3) + ((k>>2)&1)
    auto stash = [&](int s) {
        uint32_t* sA = gsm + s * 6144;
        uint32_t* sB = sA + 3072;
#pragma unroll
        for (int i = 0; i < 2; ++i) {
            const int v = tid + i * 256;
            const int row = v >> 2, cb = (v & 3) * 4;
            const int base = row * 24 + (cb & 8) + ((cb >> 2) & 1);
            uint32_t* pa = &sA[base];
            pa[0] = f2tf32(ra[i].x); pa[2] = f2tf32(ra[i].y);
            pa[4] = f2tf32(ra[i].z); pa[6] = f2tf32(ra[i].w);
            uint32_t* pb = &sB[base];
            pb[0] = f2tf32(rb[i].x); pb[2] = f2tf32(rb[i].y);
            pb[4] = f2tf32(rb[i].z); pb[6] = f2tf32(rb[i].w);
        }
    };
    auto compute = [&](int s) {
        const uint32_t* sA = gsm + s * 6144;
        const uint32_t* sB = sA + 3072;
#pragma unroll
        for (int ks = 0; ks < 16; ks += 8) {
            uint32_t af[4][4], bf[4][2];
#pragma unroll
            for (int mt = 0; mt < 4; ++mt) {
                uint2 lo = *(const uint2*)&sA[(wm + mt * 16 + g) * 24 + ks + 2 * tg];
                uint2 hi = *(const uint2*)&sA[(wm + mt * 16 + g + 8) * 24 + ks + 2 * tg];
                af[mt][0] = lo.x; af[mt][2] = lo.y;
                af[mt][1] = hi.x; af[mt][3] = hi.y;
            }
#pragma unroll
            for (int nt = 0; nt < 4; ++nt) {
                uint2 bb = *(const uint2*)&sB[(wn + nt * 8 + g) * 24 + ks + 2 * tg];
                bf[nt][0] = bb.x; bf[nt][1] = bb.y;
            }
#pragma unroll
            for (int mt = 0; mt < 4; ++mt)
#pragma unroll
                for (int nt = 0; nt < 4; ++nt) MMA_TF32(acc[mt][nt], af[mt], bf[nt]);
        }
    };

    fetch(0);
    stash(0);
    __syncthreads();

    for (int kt = 0; kt < Ee / 16; ++kt) {
        const int s = kt & 1;
        if (kt + 1 < Ee / 16) fetch(kt + 1);
        compute(s);
        if (kt + 1 < Ee / 16) stash(1 - s);
        __syncthreads();
    }

#pragma unroll
    for (int mt = 0; mt < 4; ++mt) {
#pragma unroll
        for (int i = 0; i < 2; ++i) {
            const int m = m0 + wm + mt * 16 + g + i * 8;
            const int b_ = m / Ss, srow = m % Ss;
#pragma unroll
            for (int nt = 0; nt < 4; ++nt) {
                const int n = n0 + wn + nt * 8 + tg * 2;
                float2 bv = *(const float2*)&bias[n];
                float2 r;
                r.x = acc[mt][nt][i * 2 + 0] + bv.x;
                r.y = acc[mt][nt][i * 2 + 1] + bv.y;
                if (HEAD_STORE) {
                    const int h = n >> 6, dd = n & 63;
                    *(float2*)&C[(((long)(b_ * Hh + h) * Ss + srow) * Dd) + dd] = r;
                } else {
                    *(float2*)&C[(long)m * Ee + n] = r;
                }
            }
        }
    }
}

// ---------------------------------------------------------------------------
// Tensor-core flash attention (R6):
//  - mask from pre-compressed bit tensor (broadcast LDG.64 + 2 ALU per row)
//  - deferred l reduction (per-lane partials, one shfl-reduce at epilogue)
//  - Vt/Ps pair-permuted LDS.64 layout (R5)
// ---------------------------------------------------------------------------
__global__ __launch_bounds__(256, 2) void attn_mma(const uint32_t* __restrict__ mbq,
                                                   const float* __restrict__ qh,
                                                   const float* __restrict__ kh,
                                                   const float* __restrict__ vh,
                                                   float* __restrict__ ctx) {
    extern __shared__ uint32_t dsm[];
    uint32_t* Ks = dsm;                // stride 68
    uint32_t* Vt = dsm + 64 * 68;      // stride 72, permuted cols
    uint32_t* Ps = dsm + 64 * 68 + 64 * 72;  // stride 72, permuted cols

    const int tid = threadIdx.x;
    const int lane = tid & 31;
    const int g = lane >> 2, tg = lane & 3;
    const int w = tid >> 5;
    const int q0 = blockIdx.x * 128;
    const int bh = blockIdx.y;
    const int b = bh / Hh;
    const int h = bh % Hh;

    const float* Q = qh + (long)bh * Ss * Dd;
    const float* Kg = kh + (long)bh * Ss * Dd;
    const float* Vg = vh + (long)bh * Ss * Dd;

    // Q fragments for rows r0=q0+w*16+g and r0+8, held all kernel (tf32)
    const int r0 = q0 + w * 16 + g;
    uint32_t qf[8][4];
#pragma unroll
    for (int ks = 0; ks < 8; ++ks) {
        qf[ks][0] = f2tf32(Q[(long)r0 * Dd + ks * 8 + tg]);
        qf[ks][1] = f2tf32(Q[(long)(r0 + 8) * Dd + ks * 8 + tg]);
        qf[ks][2] = f2tf32(Q[(long)r0 * Dd + ks * 8 + tg + 4]);
        qf[ks][3] = f2tf32(Q[(long)(r0 + 8) * Dd + ks * 8 + tg + 4]);
    }

    // Ps stash offsets for cols 2tg / 2tg+1 within an 8-col permuted group
    const int po0 = (((2 * tg) & 3) << 1) | ((2 * tg) >> 2);
    const int po1 = (((2 * tg + 1) & 3) << 1) | ((2 * tg + 1) >> 2);

    float oacc[8][4];
#pragma unroll
    for (int nt = 0; nt < 8; ++nt)
#pragma unroll
        for (int i = 0; i < 4; ++i) oacc[nt][i] = 0.f;
    float mrow[2] = {-1e30f, -1e30f};
    float lrow[2] = {0.f, 0.f};  // per-lane partial; reduced at epilogue

    for (int kt = 0; kt < Ss / 64; ++kt) {
        __syncthreads();  // Ks/Vt/Ps safe to overwrite
        // Stage K tile [key][d] (stride 68) and V transposed [d][key] permuted
        {
            const int r = tid >> 2;          // 0..63 key row
            const int c0 = (tid & 3) * 16;   // d offset
            const int koff = (r >> 3) * 8 + ((r & 3) << 1) + ((r >> 2) & 1);
#pragma unroll
            for (int u = 0; u < 4; ++u) {
                const int c = c0 + u * 4;
                float4 kv = *(const float4*)&Kg[(long)(kt * 64 + r) * Dd + c];
                *(uint4*)&Ks[r * 68 + c] =
                    make_uint4(f2tf32(kv.x), f2tf32(kv.y), f2tf32(kv.z), f2tf32(kv.w));
                float4 vv = *(const float4*)&Vg[(long)(kt * 64 + r) * Dd + c];
                Vt[(c + 0) * 72 + koff] = f2tf32(vv.x);
                Vt[(c + 1) * 72 + koff] = f2tf32(vv.y);
                Vt[(c + 2) * 72 + koff] = f2tf32(vv.z);
                Vt[(c + 3) * 72 + koff] = f2tf32(vv.w);
            }
        }

        // Mask bits: broadcast LDG.64 per row + field extract
        uint32_t mbits[2];
#pragma unroll
        for (int i = 0; i < 2; ++i) {
            const int row = r0 + i * 8;
            uint2 mw = *(const uint2*)&mbq[(((long)(b * Ss + row)) * 32 + kt) * 2];
            uint32_t wv = (tg & 2) ? mw.y : mw.x;
            mbits[i] = (wv >> ((tg & 1) * 16)) & 0xFFFFu;
        }
        __syncthreads();

        // QK^T: s[nt] covers keys nt*8..+8, rows r0 / r0+8
        float s[8][4];
#pragma unroll
        for (int nt = 0; nt < 8; ++nt)
#pragma unroll
            for (int i = 0; i < 4; ++i) s[nt][i] = 0.f;
#pragma unroll
        for (int ks = 0; ks < 8; ++ks) {
#pragma unroll
            for (int nt = 0; nt < 8; ++nt) {
                uint32_t bf[2];
                const uint32_t* p = &Ks[(nt * 8 + g) * 68 + ks * 8 + tg];
                bf[0] = p[0];
                bf[1] = p[4];
                MMA_TF32(s[nt], qf[ks], bf);
            }
        }

        // Mask (from mbits) + online softmax per row
#pragma unroll
        for (int i = 0; i < 2; ++i) {
            float rmax = -1e30f;
#pragma unroll
            for (int nt = 0; nt < 8; ++nt) {
                float a = ((mbits[i] >> (2 * nt)) & 1u) ? s[nt][i * 2 + 0] * 0.125f
                                                        : -1e10f;
                float c = ((mbits[i] >> (2 * nt + 1)) & 1u) ? s[nt][i * 2 + 1] * 0.125f
                                                            : -1e10f;
                s[nt][i * 2 + 0] = a;
                s[nt][i * 2 + 1] = c;
                rmax = fmaxf(rmax, fmaxf(a, c));
            }
            rmax = fmaxf(rmax, __shfl_xor_sync(0xffffffffu, rmax, 1));
            rmax = fmaxf(rmax, __shfl_xor_sync(0xffffffffu, rmax, 2));

            const float mnew = fmaxf(mrow[i], rmax);
            const float alpha = __expf(mrow[i] - mnew);
            mrow[i] = mnew;

            float rsum = 0.f;
#pragma unroll
            for (int nt = 0; nt < 8; ++nt) {
                float a = __expf(s[nt][i * 2 + 0] - mnew);
                float c = __expf(s[nt][i * 2 + 1] - mnew);
                s[nt][i * 2 + 0] = a;
                s[nt][i * 2 + 1] = c;
                rsum += a + c;
            }
            lrow[i] = lrow[i] * alpha + rsum;  // per-lane partial (no shfl)

#pragma unroll
            for (int nt = 0; nt < 8; ++nt) {
                oacc[nt][i * 2 + 0] *= alpha;
                oacc[nt][i * 2 + 1] *= alpha;
                uint32_t* pp = &Ps[(w * 16 + g + i * 8) * 72 + nt * 8];
                pp[po0] = f2tf32(s[nt][i * 2 + 0]);
                pp[po1] = f2tf32(s[nt][i * 2 + 1]);
            }
        }
        __syncwarp();  // own-warp rows only: warp-local store->load

        // PV with LDS.64 fragments (permuted pair layout)
#pragma unroll
        for (int ks = 0; ks < 8; ++ks) {
            uint32_t pf[4];
            {
                uint2 lo = *(const uint2*)&Ps[(w * 16 + g) * 72 + ks * 8 + 2 * tg];
                uint2 hi = *(const uint2*)&Ps[(w * 16 + g + 8) * 72 + ks * 8 + 2 * tg];
                pf[0] = lo.x;
                pf[2] = lo.y;
                pf[1] = hi.x;
                pf[3] = hi.y;
            }
#pragma unroll
            for (int nt = 0; nt < 8; ++nt) {
                uint2 bv = *(const uint2*)&Vt[(nt * 8 + g) * 72 + ks * 8 + 2 * tg];
                uint32_t bf[2] = {bv.x, bv.y};
                MMA_TF32(oacc[nt], pf, bf);
            }
        }
    }

    // Epilogue: reduce l across the 4-lane quad, normalize, store ctx
#pragma unroll
    for (int i = 0; i < 2; ++i) {
        float lsum = lrow[i];
        lsum += __shfl_xor_sync(0xffffffffu, lsum, 1);
        lsum += __shfl_xor_sync(0xffffffffu, lsum, 2);
        const float inv = 1.f / lsum;
        const int row = r0 + i * 8;
#pragma unroll
        for (int nt = 0; nt < 8; ++nt) {
            float2 r;
            r.x = oacc[nt][i * 2 + 0] * inv;
            r.y = oacc[nt][i * 2 + 1] * inv;
            *(float2*)&g_ctx[((long)(b * Ss + row)) * Ee + h * Dd + nt * 8 + tg * 2] = r;
        }
    }
    (void)ctx;
}

// ---------------------------------------------------------------------------
extern "C" void kernel_launch(void* const* d_in, const int* in_sizes, int n_in,
                              void* d_out, int out_size) {
    const float* q  = (const float*)d_in[0];
    const float* k  = (const float*)d_in[1];
    const float* v  = (const float*)d_in[2];
    const int* mask = (const int*)d_in[3];
    const float* Wq = (const float*)d_in[4];
    const float* bq = (const float*)d_in[5];
    const float* Wk = (const float*)d_in[6];
    const float* bk = (const float*)d_in[7];
    const float* Wv = (const float*)d_in[8];
    const float* bv = (const float*)d_in[9];
    const float* Wo = (const float*)d_in[10];
    const float* bo = (const float*)d_in[11];
    float* out = (float*)d_out;

    float *qh, *kh, *vh, *ctx;
    uint32_t* mb;
    cudaGetSymbolAddress((void**)&qh, g_qh);
    cudaGetSymbolAddress((void**)&kh, g_kh);
    cudaGetSymbolAddress((void**)&vh, g_vh);
    cudaGetSymbolAddress((void**)&ctx, g_ctx);
    cudaGetSymbolAddress((void**)&mb, g_mbits);

    mask_compress<<<Bb * Ss * 64 / 256, 256>>>(mask, mb);

    dim3 gg(Ee / 128, (Bb * Ss) / 128);  // 8 x 32
    gemm_mma<true><<<gg, 256>>>(q, Wq, bq, qh);
    gemm_mma<true><<<gg, 256>>>(k, Wk, bk, kh);
    gemm_mma<true><<<gg, 256>>>(v, Wv, bv, vh);

    const int ATTN_SMEM = (64 * 68 + 64 * 72 + 128 * 72) * 4;  // 72704 B
    cudaFuncSetAttribute(attn_mma, cudaFuncAttributeMaxDynamicSharedMemorySize,
                         ATTN_SMEM);
    dim3 gattn(Ss / 128, Bb * Hh);  // 16 x 32
    attn_mma<<<gattn, 256, ATTN_SMEM>>>(mb, qh, kh, vh, ctx);

    gemm_mma<false><<<gg, 256>>>(ctx, Wo, bo, out);
}

// round 7
// speedup vs baseline: 4.3351x; 1.4763x over previous
#include <cuda_runtime.h>
#include <cuda_fp16.h>
#include <cstdint>

// Problem constants (MultiHeadAttention: B=2,S=2048,E=1024,H=16,D=64)
constexpr int Bb = 2;
constexpr int Ss = 2048;
constexpr int Ee = 1024;
constexpr int Hh = 16;
constexpr int Dd = 64;

// Scratch (device globals; no allocation allowed)
__device__ float g_qh[Bb * Hh * Ss * Dd];   // [B,H,S,D]
__device__ float g_kh[Bb * Hh * Ss * Dd];
__device__ float g_vh[Bb * Hh * Ss * Dd];
__device__ float g_ctx[Bb * Ss * Ee];       // [B,S,E]
__device__ uint32_t g_mbits[Bb * Ss * Ss / 32];  // permuted mask bits

__device__ __forceinline__ uint32_t f2h2(float a, float b) {
    half2 h = __floats2half2_rn(a, b);  // x(lo)=a, y(hi)=b
    return *(uint32_t*)&h;
}

#define MMA_F16(c, a, b)                                                       \
    asm volatile(                                                              \
        "mma.sync.aligned.m16n8k16.row.col.f32.f16.f16.f32 "                   \
        "{%0,%1,%2,%3}, {%4,%5,%6,%7}, {%8,%9}, {%0,%1,%2,%3};"                \
        : "+f"((c)[0]), "+f"((c)[1]), "+f"((c)[2]), "+f"((c)[3])               \
        : "r"((a)[0]), "r"((a)[1]), "r"((a)[2]), "r"((a)[3]),                  \
          "r"((b)[0]), "r"((b)[1]))

// ---------------------------------------------------------------------------
// Mask bit-compression (unchanged R6; bit mapping matches k16 accum layout)
// ---------------------------------------------------------------------------
__global__ __launch_bounds__(256) void mask_compress(const int* __restrict__ mask,
                                                     uint32_t* __restrict__ out) {
    const int idx = blockIdx.x * 256 + threadIdx.x;  // B*S*32*2
    const int h = idx & 1;
    const int kt = (idx >> 1) & 31;
    const int br = idx >> 6;
    const int* p = mask + (long)br * Ss + kt * 64 + 4 * h;
    uint32_t bits = 0;
#pragma unroll
    for (int nt = 0; nt < 8; ++nt) {
        int4 m = *(const int4*)&p[nt * 8];
        bits |= (m.x ? 1u : 0u) << (2 * nt);
        bits |= (m.y ? 1u : 0u) << (2 * nt + 1);
        bits |= (m.z ? 1u : 0u) << (16 + 2 * nt);
        bits |= (m.w ? 1u : 0u) << (16 + 2 * nt + 1);
    }
    out[idx] = bits;
}

// ---------------------------------------------------------------------------
// fp16 m16n8k16 GEMM: C[m,n] = sum_k A[m,k]*W[n,k] + bias[n]
// CTA 128x128, BK=16, 8 warps (2x4), warp tile 64x32. Double-buffered.
// Smem rows: 16 halves permuted (k -> pair (k&7 even pair, +8)), stride 24
// words -> all fragment loads conflict-free 8B-aligned LDS.64.
// ---------------------------------------------------------------------------
template <bool HEAD_STORE>
__global__ __launch_bounds__(256) void gemm_mma(const float* __restrict__ A,
                                                const float* __restrict__ W,
                                                const float* __restrict__ bias,
                                                float* __restrict__ C) {
    __shared__ uint32_t gsm[12288];  // [A0|B0|A1|B1] 3072 words each (48KB)

    const int tid = threadIdx.x;
    const int lane = tid & 31;
    const int g = lane >> 2, tg = lane & 3;
    const int w = tid >> 5;
    const int wm = (w >> 2) * 64;
    const int wn = (w & 3) * 32;
    const int m0 = blockIdx.y * 128, n0 = blockIdx.x * 128;

    float acc[4][4][4];
#pragma unroll
    for (int mt = 0; mt < 4; ++mt)
#pragma unroll
        for (int nt = 0; nt < 4; ++nt)
#pragma unroll
            for (int i = 0; i < 4; ++i) acc[mt][nt][i] = 0.f;

    float4 ra[2], rb[2];

    auto fetch = [&](int kt) {
        const int kb = kt * 16;
#pragma unroll
        for (int i = 0; i < 2; ++i) {
            const int v = tid + i * 256;
            const int row = v >> 2, c = (v & 3) * 4;
            ra[i] = *(const float4*)&A[(long)(m0 + row) * Ee + kb + c];
            rb[i] = *(const float4*)&W[(long)(n0 + row) * Ee + kb + c];
        }
    };
    // halves (k,k+1)@word w1, (k+2,k+3)@w1+2 with w1 = (c&7)+(c>>3)
    auto stash = [&](int s) {
        uint32_t* sA = gsm + s * 6144;
        uint32_t* sB = sA + 3072;
#pragma unroll
        for (int i = 0; i < 2; ++i) {
            const int v = tid + i * 256;
            const int row = v >> 2, c = (v & 3) * 4;
            const int w1 = (c & 7) + (c >> 3);
            uint32_t* pa = &sA[row * 24 + w1];
            pa[0] = f2h2(ra[i].x, ra[i].y);
            pa[2] = f2h2(ra[i].z, ra[i].w);
            uint32_t* pb = &sB[row * 24 + w1];
            pb[0] = f2h2(rb[i].x, rb[i].y);
            pb[2] = f2h2(rb[i].z, rb[i].w);
        }
    };
    auto compute = [&](int s) {
        const uint32_t* sA = gsm + s * 6144;
        const uint32_t* sB = sA + 3072;
        uint32_t af[4][4], bf[4][2];
#pragma unroll
        for (int mt = 0; mt < 4; ++mt) {
            uint2 lo = *(const uint2*)&sA[(wm + mt * 16 + g) * 24 + 2 * tg];
            uint2 hi = *(const uint2*)&sA[(wm + mt * 16 + g + 8) * 24 + 2 * tg];
            af[mt][0] = lo.x; af[mt][1] = hi.x;
            af[mt][2] = lo.y; af[mt][3] = hi.y;
        }
#pragma unroll
        for (int nt = 0; nt < 4; ++nt) {
            uint2 bb = *(const uint2*)&sB[(wn + nt * 8 + g) * 24 + 2 * tg];
            bf[nt][0] = bb.x; bf[nt][1] = bb.y;
        }
#pragma unroll
        for (int mt = 0; mt < 4; ++mt)
#pragma unroll
            for (int nt = 0; nt < 4; ++nt) MMA_F16(acc[mt][nt], af[mt], bf[nt]);
    };

    fetch(0);
    stash(0);
    __syncthreads();

    for (int kt = 0; kt < Ee / 16; ++kt) {
        const int s = kt & 1;
        if (kt + 1 < Ee / 16) fetch(kt + 1);
        compute(s);
        if (kt + 1 < Ee / 16) stash(1 - s);
        __syncthreads();
    }

#pragma unroll
    for (int mt = 0; mt < 4; ++mt) {
#pragma unroll
        for (int i = 0; i < 2; ++i) {
            const int m = m0 + wm + mt * 16 + g + i * 8;
            const int b_ = m / Ss, srow = m % Ss;
#pragma unroll
            for (int nt = 0; nt < 4; ++nt) {
                const int n = n0 + wn + nt * 8 + tg * 2;
                float2 bv = *(const float2*)&bias[n];
                float2 r;
                r.x = acc[mt][nt][i * 2 + 0] + bv.x;
                r.y = acc[mt][nt][i * 2 + 1] + bv.y;
                if (HEAD_STORE) {
                    const int h = n >> 6, dd = n & 63;
                    *(float2*)&C[(((long)(b_ * Hh + h) * Ss + srow) * Dd) + dd] = r;
                } else {
                    *(float2*)&C[(long)m * Ee + n] = r;
                }
            }
        }
    }
}

// ---------------------------------------------------------------------------
// fp16 tensor-core flash attention. CTA = 128 queries x key sweep, 8 warps.
// Smem (words): Ks[64 keys][40] @0, Vt[64 d][40] @2560, Ps[128 q][40] @5120
// All rows hold 64 halves (4 perm k16-groups x 8 words) + pad; stride 40
// -> conflict-free LDS.64 fragments (banks 8g+2tg).
// ---------------------------------------------------------------------------
__global__ __launch_bounds__(256, 2) void attn_mma(const uint32_t* __restrict__ mbq,
                                                   const float* __restrict__ qh,
                                                   const float* __restrict__ kh,
                                                   const float* __restrict__ vh,
                                                   float* __restrict__ ctx) {
    extern __shared__ uint32_t dsm[];
    uint32_t* Ks = dsm;             // [key][d]  (B-frag for QK)
    uint32_t* Vt = dsm + 2560;      // [d][key]  (B-frag for PV)
    uint32_t* Ps = dsm + 5120;      // [qrow][key] (A-frag for PV)

    const int tid = threadIdx.x;
    const int lane = tid & 31;
    const int g = lane >> 2, tg = lane & 3;
    const int w = tid >> 5;
    const int q0 = blockIdx.x * 128;
    const int bh = blockIdx.y;
    const int b = bh / Hh;
    const int h = bh % Hh;

    const float* Q = qh + (long)bh * Ss * Dd;
    const float* Kg = kh + (long)bh * Ss * Dd;
    const float* Vg = vh + (long)bh * Ss * Dd;

    // Q fragments (fp16) rows r0, r0+8; 4 k16-steps over d=64
    const int r0 = q0 + w * 16 + g;
    uint32_t qf[4][4];
#pragma unroll
    for (int ks = 0; ks < 4; ++ks) {
        float2 a = *(const float2*)&Q[(long)r0 * Dd + ks * 16 + 2 * tg];
        float2 b2 = *(const float2*)&Q[(long)(r0 + 8) * Dd + ks * 16 + 2 * tg];
        float2 c = *(const float2*)&Q[(long)r0 * Dd + ks * 16 + 2 * tg + 8];
        float2 d = *(const float2*)&Q[(long)(r0 + 8) * Dd + ks * 16 + 2 * tg + 8];
        qf[ks][0] = f2h2(a.x, a.y);
        qf[ks][1] = f2h2(b2.x, b2.y);
        qf[ks][2] = f2h2(c.x, c.y);
        qf[ks][3] = f2h2(d.x, d.y);
    }

    float oacc[8][4];
#pragma unroll
    for (int nt = 0; nt < 8; ++nt)
#pragma unroll
        for (int i = 0; i < 4; ++i) oacc[nt][i] = 0.f;
    float mrow[2] = {-1e30f, -1e30f};
    float lrow[2] = {0.f, 0.f};

    // V staging: half index within a row for this thread's key r
    const int vr = tid >> 2;          // key row 0..63
    const int vc0 = (tid & 3) * 16;   // d offset
    const int vrr = vr & 15;
    const int vkidx = (((vr >> 4) * 8) + 2 * ((vrr & 7) >> 1) + (vrr >> 3)) * 2 +
                      (vrr & 1);

    for (int kt = 0; kt < Ss / 64; ++kt) {
        __syncthreads();  // tiles safe to overwrite
        // Stage K [key][d] and V transposed [d][key], both perm fp16
        {
            half* Vh = (half*)Vt;
#pragma unroll
            for (int u = 0; u < 4; ++u) {
                const int c = vc0 + u * 4;
                const int w1 = (c & 7) + ((c >> 3) & 1);
                const int jg = (c >> 4) * 8;
                float4 kv = *(const float4*)&Kg[(long)(kt * 64 + vr) * Dd + c];
                uint32_t* pk = &Ks[vr * 40 + jg + w1];
                pk[0] = f2h2(kv.x, kv.y);
                pk[2] = f2h2(kv.z, kv.w);
                float4 vv = *(const float4*)&Vg[(long)(kt * 64 + vr) * Dd + c];
                Vh[(c + 0) * 80 + vkidx] = __float2half_rn(vv.x);
                Vh[(c + 1) * 80 + vkidx] = __float2half_rn(vv.y);
                Vh[(c + 2) * 80 + vkidx] = __float2half_rn(vv.z);
                Vh[(c + 3) * 80 + vkidx] = __float2half_rn(vv.w);
            }
        }

        // Mask bits: broadcast LDG.64 per row + field extract
        uint32_t mbits[2];
#pragma unroll
        for (int i = 0; i < 2; ++i) {
            const int row = r0 + i * 8;
            uint2 mw = *(const uint2*)&mbq[(((long)(b * Ss + row)) * 32 + kt) * 2];
            uint32_t wv = (tg & 2) ? mw.y : mw.x;
            mbits[i] = (wv >> ((tg & 1) * 16)) & 0xFFFFu;
        }
        __syncthreads();

        // QK^T: 4 k16-steps x 8 key-groups
        float s[8][4];
#pragma unroll
        for (int nt = 0; nt < 8; ++nt)
#pragma unroll
            for (int i = 0; i < 4; ++i) s[nt][i] = 0.f;
#pragma unroll
        for (int ks = 0; ks < 4; ++ks) {
#pragma unroll
            for (int nt = 0; nt < 8; ++nt) {
                uint2 bb = *(const uint2*)&Ks[(nt * 8 + g) * 40 + ks * 8 + 2 * tg];
                uint32_t bf[2] = {bb.x, bb.y};
                MMA_F16(s[nt], qf[ks], bf);
            }
        }

        // Mask + online softmax per row (cols nt*8+2tg, +1 — same as R6)
#pragma unroll
        for (int i = 0; i < 2; ++i) {
            float rmax = -1e30f;
#pragma unroll
            for (int nt = 0; nt < 8; ++nt) {
                float a = ((mbits[i] >> (2 * nt)) & 1u) ? s[nt][i * 2 + 0] * 0.125f
                                                        : -1e10f;
                float c = ((mbits[i] >> (2 * nt + 1)) & 1u) ? s[nt][i * 2 + 1] * 0.125f
                                                            : -1e10f;
                s[nt][i * 2 + 0] = a;
                s[nt][i * 2 + 1] = c;
                rmax = fmaxf(rmax, fmaxf(a, c));
            }
            rmax = fmaxf(rmax, __shfl_xor_sync(0xffffffffu, rmax, 1));
            rmax = fmaxf(rmax, __shfl_xor_sync(0xffffffffu, rmax, 2));

            const float mnew = fmaxf(mrow[i], rmax);
            const float alpha = __expf(mrow[i] - mnew);
            mrow[i] = mnew;

            float rsum = 0.f;
#pragma unroll
            for (int nt = 0; nt < 8; ++nt) {
                float a = __expf(s[nt][i * 2 + 0] - mnew);
                float c = __expf(s[nt][i * 2 + 1] - mnew);
                s[nt][i * 2 + 0] = a;
                s[nt][i * 2 + 1] = c;
                rsum += a + c;
            }
            lrow[i] = lrow[i] * alpha + rsum;

#pragma unroll
            for (int nt = 0; nt < 8; ++nt) {
                oacc[nt][i * 2 + 0] *= alpha;
                oacc[nt][i * 2 + 1] *= alpha;
                // P half2 (keys nt*8+2tg, +1) -> word j*8 + 2tg + (nt&1)
                Ps[(w * 16 + g + i * 8) * 40 + (nt >> 1) * 8 + 2 * tg + (nt & 1)] =
                    f2h2(s[nt][i * 2 + 0], s[nt][i * 2 + 1]);
            }
        }
        __syncwarp();  // own-warp rows only

        // PV: 4 k16-steps (keys) x 8 d-groups
#pragma unroll
        for (int ks = 0; ks < 4; ++ks) {
            uint2 lo = *(const uint2*)&Ps[(w * 16 + g) * 40 + ks * 8 + 2 * tg];
            uint2 hi = *(const uint2*)&Ps[(w * 16 + g + 8) * 40 + ks * 8 + 2 * tg];
            uint32_t pf[4] = {lo.x, hi.x, lo.y, hi.y};
#pragma unroll
            for (int nt = 0; nt < 8; ++nt) {
                uint2 bv = *(const uint2*)&Vt[(nt * 8 + g) * 40 + ks * 8 + 2 * tg];
                uint32_t bf[2] = {bv.x, bv.y};
                MMA_F16(oacc[nt], pf, bf);
            }
        }
    }

    // Epilogue: reduce l across quad, normalize, store ctx
#pragma unroll
    for (int i = 0; i < 2; ++i) {
        float lsum = lrow[i];
        lsum += __shfl_xor_sync(0xffffffffu, lsum, 1);
        lsum += __shfl_xor_sync(0xffffffffu, lsum, 2);
        const float inv = 1.f / lsum;
        const int row = r0 + i * 8;
#pragma unroll
        for (int nt = 0; nt < 8; ++nt) {
            float2 r;
            r.x = oacc[nt][i * 2 + 0] * inv;
            r.y = oacc[nt][i * 2 + 1] * inv;
            *(float2*)&g_ctx[((long)(b * Ss + row)) * Ee + h * Dd + nt * 8 + tg * 2] = r;
        }
    }
    (void)ctx;
}

// ---------------------------------------------------------------------------
extern "C" void kernel_launch(void* const* d_in, const int* in_sizes, int n_in,
                              void* d_out, int out_size) {
    const float* q  = (const float*)d_in[0];
    const float* k  = (const float*)d_in[1];
    const float* v  = (const float*)d_in[2];
    const int* mask = (const int*)d_in[3];
    const float* Wq = (const float*)d_in[4];
    const float* bq = (const float*)d_in[5];
    const float* Wk = (const float*)d_in[6];
    const float* bk = (const float*)d_in[7];
    const float* Wv = (const float*)d_in[8];
    const float* bv = (const float*)d_in[9];
    const float* Wo = (const float*)d_in[10];
    const float* bo = (const float*)d_in[11];
    float* out = (float*)d_out;

    float *qh, *kh, *vh, *ctx;
    uint32_t* mb;
    cudaGetSymbolAddress((void**)&qh, g_qh);
    cudaGetSymbolAddress((void**)&kh, g_kh);
    cudaGetSymbolAddress((void**)&vh, g_vh);
    cudaGetSymbolAddress((void**)&ctx, g_ctx);
    cudaGetSymbolAddress((void**)&mb, g_mbits);

    mask_compress<<<Bb * Ss * 64 / 256, 256>>>(mask, mb);

    dim3 gg(Ee / 128, (Bb * Ss) / 128);  // 8 x 32
    gemm_mma<true><<<gg, 256>>>(q, Wq, bq, qh);
    gemm_mma<true><<<gg, 256>>>(k, Wk, bk, kh);
    gemm_mma<true><<<gg, 256>>>(v, Wv, bv, vh);

    const int ATTN_SMEM = (2560 + 2560 + 5120) * 4;  // 40960 B
    cudaFuncSetAttribute(attn_mma, cudaFuncAttributeMaxDynamicSharedMemorySize,
                         ATTN_SMEM);
    dim3 gattn(Ss / 128, Bb * Hh);  // 16 x 32
    attn_mma<<<gattn, 256, ATTN_SMEM>>>(mb, qh, kh, vh, ctx);

    gemm_mma<false><<<gg, 256>>>(ctx, Wo, bo, out);
}